// round 15
// baseline (speedup 1.0000x reference)
#include <cuda_runtime.h>
#include <cuda_bf16.h>

// ProdLayer: out[i] = prod_{j : csr[j]==i} x[ptrs[j]], empty segments -> 0.
// csr sorted ascending, csr[E-1] == S-1 => contiguous runs.
//
// R9 (resubmit after infra failure): EPT=8 persistent loop + software-
// pipelined index loads: tile i+1's csr/ptrs int4 loads are issued while
// tile i's gathers/scan execute, so in steady state gathers issue
// immediately at each iteration start.

#define EPT 8

struct Tile { int4 ka, kb, pa, pb; };

__device__ __forceinline__ Tile load_tile(const int* __restrict__ csr,
                                          const int* __restrict__ ptrs,
                                          int b, int E)
{
    Tile t;
    if (b + EPT - 1 < E) {
        t.ka = __ldcs(reinterpret_cast<const int4*>(csr  + b));
        t.kb = __ldcs(reinterpret_cast<const int4*>(csr  + b + 4));
        t.pa = __ldcs(reinterpret_cast<const int4*>(ptrs + b));
        t.pb = __ldcs(reinterpret_cast<const int4*>(ptrs + b + 4));
    } else {                        // tail / out-of-range: sentinel fill
        int k[EPT], p[EPT];
        #pragma unroll
        for (int m = 0; m < EPT; ++m) {
            if (b + m < E) { k[m] = __ldg(&csr[b + m]); p[m] = __ldg(&ptrs[b + m]); }
            else           { k[m] = -2;                 p[m] = 0; }
        }
        t.ka = make_int4(k[0], k[1], k[2], k[3]);
        t.kb = make_int4(k[4], k[5], k[6], k[7]);
        t.pa = make_int4(p[0], p[1], p[2], p[3]);
        t.pb = make_int4(p[4], p[5], p[6], p[7]);
    }
    return t;
}

__global__ void __launch_bounds__(256)
prod_seg8pp_kernel(const float* __restrict__ x,
                   const int*   __restrict__ ptrs,
                   const int*   __restrict__ csr,
                   float*       __restrict__ out,
                   int E)
{
    const unsigned FULL = 0xffffffffu;
    int lane   = threadIdx.x & 31;
    int stride = gridDim.x * blockDim.x * EPT;
    int b0     = (blockIdx.x * blockDim.x + threadIdx.x) * EPT;

    Tile cur = load_tile(csr, ptrs, b0, E);

    for (int b = b0; b - lane * EPT < E; b += stride)
    {
        // Unpack keys and issue gathers for the CURRENT tile first.
        int K[EPT] = { cur.ka.x, cur.ka.y, cur.ka.z, cur.ka.w,
                       cur.kb.x, cur.kb.y, cur.kb.z, cur.kb.w };
        int Pt[EPT] = { cur.pa.x, cur.pa.y, cur.pa.z, cur.pa.w,
                        cur.pb.x, cur.pb.y, cur.pb.z, cur.pb.w };
        float X[EPT];
        #pragma unroll
        for (int m = 0; m < EPT; ++m)
            X[m] = (K[m] != -2) ? __ldg(&x[Pt[m]]) : 1.0f;

        // Prefetch NEXT tile's index data (overlaps gathers + scan below).
        Tile nxt = load_tile(csr, ptrs, b + stride, E);

        bool valid = (b < E);

        // Key of last valid edge in this thread (-2 if none).
        int kt = -2;
        #pragma unroll
        for (int m = 0; m < EPT; ++m) if (K[m] != -2) kt = K[m];

        // Suffix-run products: P[m] = prod of X over m's run starting at m.
        float P[EPT];
        P[EPT - 1] = X[EPT - 1];
        #pragma unroll
        for (int m = EPT - 2; m >= 0; --m)
            P[m] = X[m] * ((K[m + 1] == K[m]) ? P[m + 1] : 1.0f);

        // s = product of trailing run = P[first index whose key == kt].
        float s = 1.0f;
        #pragma unroll
        for (int m = EPT - 1; m >= 0; --m) if (K[m] == kt) s = P[m];

        // g = prefix-run product for key K[0].
        float g = X[0];
        #pragma unroll
        for (int m = 1; m < EPT; ++m) g *= (K[m] == K[0]) ? X[m] : 1.0f;

        // prev = key of edge b-1.
        int prev = __shfl_up_sync(FULL, kt, 1);
        if (lane == 0) prev = (b > 0) ? __ldg(&csr[b - 1]) : -1;

        // Warp segmented suffix scan over thread aggregates.
        int   K0 = K[0];
        float V = s, G = g;
        #pragma unroll
        for (int d = 1; d < 32; d <<= 1) {
            int   kd = __shfl_down_sync(FULL, K0, d);
            float Gd = __shfl_down_sync(FULL, G,  d);
            bool src = (lane + d) < 32;
            if (src && kd == kt) V *= Gd;     // trailing run extends into t+d
            if (src && kd == K0) G *= Gd;     // prefix run spans the window
        }

        int kLast = __shfl_sync(FULL, kt, 31);

        // Cross-warp continuation: only the head of the warp-trailing run.
        if (valid && (K0 != kt || prev != kt) && kt == kLast) {
            int e = b - lane * EPT + 32 * EPT;   // first edge after this warp-tile
            while (e < E && __ldg(&csr[e]) == kt) {
                V *= __ldg(&x[__ldg(&ptrs[e])]);
                ++e;
            }
        }

        if (valid) {
            // Emit: zero-fill empty-id gaps, write run products.
            int p = prev;
            #pragma unroll
            for (int m = 0; m < EPT; ++m) {
                int km = K[m];
                if (km >= 0 && km != p) {
                    for (int i = p + 1; i < km; ++i) out[i] = 0.0f;
                    out[km] = (km == kt) ? V : P[m];
                }
                if (km >= 0) p = km;
            }
        }

        cur = nxt;
    }
}

extern "C" void kernel_launch(void* const* d_in, const int* in_sizes, int n_in,
                              void* d_out, int out_size)
{
    const float* x    = (const float*)d_in[0];
    const int*   ptrs = (const int*)  d_in[1];
    const int*   csr  = (const int*)  d_in[2];
    float*       out  = (float*)      d_out;

    int E = in_sizes[1];

    int block = 256;
    int grid  = 152 * 8;
    prod_seg8pp_kernel<<<grid, block>>>(x, ptrs, csr, out, E);
}

// round 17
// speedup vs baseline: 1.0704x; 1.0704x over previous
#include <cuda_runtime.h>
#include <cuda_bf16.h>

// ProdLayer: out[i] = prod_{j : csr[j]==i} x[ptrs[j]], empty segments -> 0.
// csr sorted ascending, csr[E-1] == S-1 => contiguous runs.
//
// R10: EPT=8 one-shot grid (best-known R6 operating point: regs<=32, high
// occupancy feeds the L1 queue). Fast path for warps whose full 256-edge
// tile is in range: no sentinel selects, kt = K[7] directly. Tail warp(s)
// take the generic guarded path.

#define EPT 8

__device__ __forceinline__ void
process_tile(const float* __restrict__ x,
             const int*   __restrict__ ptrs,
             const int*   __restrict__ csr,
             float*       __restrict__ out,
             int E, int b, int lane, bool full_tile)
{
    const unsigned FULL = 0xffffffffu;

    int   K[EPT];
    float X[EPT];
    int   kt;

    if (full_tile) {
        int4 ka = *reinterpret_cast<const int4*>(csr  + b);
        int4 kb = *reinterpret_cast<const int4*>(csr  + b + 4);
        int4 pa = *reinterpret_cast<const int4*>(ptrs + b);
        int4 pb = *reinterpret_cast<const int4*>(ptrs + b + 4);
        K[0]=ka.x; K[1]=ka.y; K[2]=ka.z; K[3]=ka.w;
        K[4]=kb.x; K[5]=kb.y; K[6]=kb.z; K[7]=kb.w;
        X[0]=__ldg(&x[pa.x]); X[1]=__ldg(&x[pa.y]);
        X[2]=__ldg(&x[pa.z]); X[3]=__ldg(&x[pa.w]);
        X[4]=__ldg(&x[pb.x]); X[5]=__ldg(&x[pb.y]);
        X[6]=__ldg(&x[pb.z]); X[7]=__ldg(&x[pb.w]);
        kt = K[EPT - 1];
    } else {
        #pragma unroll
        for (int m = 0; m < EPT; ++m) { K[m] = -2; X[m] = 1.0f; }
        bool valid = (b < E);
        if (valid) {
            #pragma unroll
            for (int m = 0; m < EPT; ++m) {
                if (b + m < E) {
                    K[m] = __ldg(&csr[b + m]);
                    X[m] = __ldg(&x[__ldg(&ptrs[b + m])]);
                }
            }
        }
        kt = -2;
        #pragma unroll
        for (int m = 0; m < EPT; ++m) if (K[m] != -2) kt = K[m];
    }

    // Suffix-run products: P[m] = prod of X over m's run starting at m.
    float P[EPT];
    P[EPT - 1] = X[EPT - 1];
    #pragma unroll
    for (int m = EPT - 2; m >= 0; --m)
        P[m] = X[m] * ((K[m + 1] == K[m]) ? P[m + 1] : 1.0f);

    // s = product of trailing run = P[first index whose key == kt].
    float s = 1.0f;
    #pragma unroll
    for (int m = EPT - 1; m >= 0; --m) if (K[m] == kt) s = P[m];

    // g = prefix-run product for key K[0].
    float g = X[0];
    #pragma unroll
    for (int m = 1; m < EPT; ++m) g *= (K[m] == K[0]) ? X[m] : 1.0f;

    // prev = key of edge b-1.
    int prev = __shfl_up_sync(FULL, kt, 1);
    if (lane == 0) prev = (b > 0) ? __ldg(&csr[b - 1]) : -1;

    // Warp segmented suffix scan over thread aggregates.
    int   K0 = K[0];
    float V = s, G = g;
    #pragma unroll
    for (int d = 1; d < 32; d <<= 1) {
        int   kd = __shfl_down_sync(FULL, K0, d);
        float Gd = __shfl_down_sync(FULL, G,  d);
        bool src = (lane + d) < 32;
        if (src && kd == kt) V *= Gd;     // trailing run extends into t+d
        if (src && kd == K0) G *= Gd;     // prefix run spans the window
    }

    int kLast = __shfl_sync(FULL, kt, 31);

    // Cross-warp continuation: only the head of the warp-trailing run.
    bool valid = (b < E);
    if (valid && (K0 != kt || prev != kt) && kt == kLast) {
        int e = b - lane * EPT + 32 * EPT;   // first edge after this warp-tile
        while (e < E && __ldg(&csr[e]) == kt) {
            V *= __ldg(&x[__ldg(&ptrs[e])]);
            ++e;
        }
    }

    if (!valid) return;

    // Emit: zero-fill empty-id gaps, write run products.
    int p = prev;
    #pragma unroll
    for (int m = 0; m < EPT; ++m) {
        int km = K[m];
        if (km >= 0 && km != p) {
            for (int i = p + 1; i < km; ++i) out[i] = 0.0f;
            out[km] = (km == kt) ? V : P[m];
        }
        if (km >= 0) p = km;
    }
}

__global__ void __launch_bounds__(256, 8)
prod_seg8f_kernel(const float* __restrict__ x,
                  const int*   __restrict__ ptrs,
                  const int*   __restrict__ csr,
                  float*       __restrict__ out,
                  int E)
{
    int t    = blockIdx.x * blockDim.x + threadIdx.x;
    int lane = threadIdx.x & 31;
    int b    = t * EPT;

    // Whole warp's 256-edge tile in range? (uniform across the warp)
    int warp_first = b - lane * EPT;
    bool full_tile = (warp_first + 32 * EPT) <= E;

    if (full_tile)
        process_tile(x, ptrs, csr, out, E, b, lane, true);
    else
        process_tile(x, ptrs, csr, out, E, b, lane, false);
}

extern "C" void kernel_launch(void* const* d_in, const int* in_sizes, int n_in,
                              void* d_out, int out_size)
{
    const float* x    = (const float*)d_in[0];
    const int*   ptrs = (const int*)  d_in[1];
    const int*   csr  = (const int*)  d_in[2];
    float*       out  = (float*)      d_out;

    int E = in_sizes[1];
    int nthreads = (E + EPT - 1) / EPT;
    int block = 256;
    int grid  = (nthreads + block - 1) / block;
    prod_seg8f_kernel<<<grid, block>>>(x, ptrs, csr, out, E);
}